// round 17
// baseline (speedup 1.0000x reference)
#include <cuda_runtime.h>
#include <math.h>

// Problem constants
#define BB   32
#define SS   1024
#define HH   2
#define EE   4
#define FF   16
#define VV   8
#define NT   (BB * SS)      // 32768 tokens
#define NCT  (BB * VV)      // 256 class tokens

typedef unsigned long long u64;

// Key structural facts exploited:
//  - No positional encoding: attention output for position s depends only on
//    (batch, token_class(s)) and the per-batch class histogram.
//  - V=8: at most 8 distinct residual-stream values per batch at every depth.
// Whole network runs on 32x8 "class tokens"; positions enter only via the
// histogram (exact regrouping: sum_j exp(q.k_cj) = sum_c count_c exp(q.k_c)).
// Kernel 1 (one block): atomic-free ballot/field histogram + class network.
// Kernel 2: positionwise gather. No cross-block sync anywhere.

__device__ float4 g_logits[NCT * 2];   // [b][class][8 vocab] as 2x float4

__device__ __forceinline__ float ex2f(float x) {
    float r;
    asm("ex2.approx.f32 %0, %1;" : "=f"(r) : "f"(x));
    return r;
}

__device__ __forceinline__ void layernorm4(const float* x, const float* __restrict__ g,
                                           const float* __restrict__ b, float* h) {
    float mu = 0.25f * (x[0] + x[1] + x[2] + x[3]);
    float d0 = x[0] - mu, d1 = x[1] - mu, d2 = x[2] - mu, d3 = x[3] - mu;
    float var = 0.25f * (d0 * d0 + d1 * d1 + d2 * d2 + d3 * d3);
    float r = rsqrtf(var + 1e-5f);
    h[0] = d0 * r * __ldg(g + 0) + __ldg(b + 0);
    h[1] = d1 * r * __ldg(g + 1) + __ldg(b + 1);
    h[2] = d2 * r * __ldg(g + 2) + __ldg(b + 2);
    h[3] = d3 * r * __ldg(g + 3) + __ldg(b + 3);
}

__device__ __forceinline__ float gelu_exact(float x) {
    return 0.5f * x * (1.0f + erff(x * 0.70710678118654752f));
}

// ---------------------------------------------------------------------------
// Kernel 1: ONE block, 256 threads. Histogram (atomic-free) + class network.
// Thread tid: batch b = tid>>3, 8 threads per batch, 128 tokens each.
// ---------------------------------------------------------------------------
__global__ void __launch_bounds__(NCT) classnet_kernel(
        const int*   __restrict__ token_ids,
        const float* __restrict__ emb,
        const float* __restrict__ ln1_g, const float* __restrict__ ln1_b,
        const float* __restrict__ wqkv,  const float* __restrict__ wo,
        const float* __restrict__ ln2_g, const float* __restrict__ ln2_b,
        const float* __restrict__ w1,    const float* __restrict__ b1,
        const float* __restrict__ w2,    const float* __restrict__ b2,
        const float* __restrict__ out_w) {
    __shared__ float2 sk[HH][NCT];
    __shared__ float2 sv[HH][NCT];
    __shared__ float  scnt[NCT];

    const int tid  = threadIdx.x;
    const int b    = tid >> 3;       // batch 0..31
    const int part = tid & 7;        // 8-thread group within batch
    const int c    = part;           // this thread's class token

    // ---- Phase A: histogram, 8-bit field accumulation (128 tokens max) ----
    {
        const int4* T = (const int4*)(token_ids + b * SS + part * (SS / 8));
        u64 acc = 0;
#pragma unroll
        for (int i = 0; i < SS / 8 / 4; i++) {   // 32 int4 loads
            int4 tt = __ldg(T + i);
            acc += (1ULL << (tt.x * 8)) + (1ULL << (tt.y * 8)) +
                   (1ULL << (tt.z * 8)) + (1ULL << (tt.w * 8));
        }
        // expand to 16-bit fields (classes 0-3 in lo, 4-7 in hi)
        u64 lo = 0, hi = 0;
#pragma unroll
        for (int cc = 0; cc < 4; cc++) {
            lo |= ((acc >> (8 * cc))       & 0xFFULL) << (16 * cc);
            hi |= ((acc >> (8 * (cc + 4))) & 0xFFULL) << (16 * cc);
        }
        // reduce over the 8-thread group (same warp, consecutive lanes)
#pragma unroll
        for (int s = 1; s < 8; s <<= 1) {
            lo += __shfl_xor_sync(0xFFFFFFFFu, lo, s);
            hi += __shfl_xor_sync(0xFFFFFFFFu, hi, s);
        }
        // every thread in the group now has the batch totals; write one each
        u64 src = (part < 4) ? lo : hi;
        scnt[tid] = (float)((src >> (16 * (part & 3))) & 0xFFFFULL);
    }
    __syncthreads();

    // ---- Phase B: class network (identical math to reference, regrouped) ---
    const int base = b * VV;
    float x[EE];
#pragma unroll
    for (int e = 0; e < EE; e++) x[e] = __ldg(emb + c * EE + e);

    const float qs = 0.70710678118654752f * 1.4426950408889634f; // 1/sqrt(D)*log2e

#pragma unroll
    for (int l = 0; l < 2; l++) {
        float h[EE];
        layernorm4(x, ln1_g + l * EE, ln1_b + l * EE, h);
        const float* wq = wqkv + l * 3 * EE * EE;
        float acc[12];
#pragma unroll
        for (int f = 0; f < 12; f++) {
            const float* w = wq + f * EE;
            acc[f] = h[0] * __ldg(w) + h[1] * __ldg(w + 1) +
                     h[2] * __ldg(w + 2) + h[3] * __ldg(w + 3);
        }
        float2 q0 = make_float2(acc[0] * qs, acc[1] * qs);
        float2 q1 = make_float2(acc[2] * qs, acc[3] * qs);
        sk[0][tid] = make_float2(acc[4], acc[5]);
        sk[1][tid] = make_float2(acc[6], acc[7]);
        sv[0][tid] = make_float2(acc[8], acc[9]);
        sv[1][tid] = make_float2(acc[10], acc[11]);
        __syncthreads();

        // count-weighted attention over 8 classes (no shift needed:
        // LN-bounded scores keep exp2 args ~|35|, far from fp32 limits)
        float o[EE];
#pragma unroll
        for (int hh = 0; hh < HH; hh++) {
            float2 q = hh ? q1 : q0;
            float S = 0.f, ox = 0.f, oy = 0.f;
#pragma unroll
            for (int cc = 0; cc < VV; cc++) {
                float2 kk = sk[hh][base + cc];
                float2 vv = sv[hh][base + cc];
                float w = scnt[base + cc] * ex2f(fmaf(q.x, kk.x, q.y * kk.y));
                S  += w;
                ox = fmaf(w, vv.x, ox);
                oy = fmaf(w, vv.y, oy);
            }
            float r = __frcp_rn(S);
            o[hh * 2 + 0] = ox * r;
            o[hh * 2 + 1] = oy * r;
        }
        __syncthreads();   // reads done before next layer overwrites smem

        // x += wo @ o
        const float* wol = wo + l * EE * EE;
#pragma unroll
        for (int f = 0; f < EE; f++) {
            const float* w = wol + f * EE;
            x[f] += o[0] * __ldg(w) + o[1] * __ldg(w + 1) +
                    o[2] * __ldg(w + 2) + o[3] * __ldg(w + 3);
        }

        // FFN
        float h2[EE];
        layernorm4(x, ln2_g + l * EE, ln2_b + l * EE, h2);
        float f1[FF];
        const float* w1l = w1 + l * FF * EE;
#pragma unroll
        for (int f = 0; f < FF; f++) {
            const float* w = w1l + f * EE;
            float a = __ldg(b1 + l * FF + f) +
                      h2[0] * __ldg(w) + h2[1] * __ldg(w + 1) +
                      h2[2] * __ldg(w + 2) + h2[3] * __ldg(w + 3);
            f1[f] = gelu_exact(a);
        }
        const float* w2l = w2 + l * EE * FF;
#pragma unroll
        for (int e = 0; e < EE; e++) {
            const float* w = w2l + e * FF;
            float a = __ldg(b2 + l * EE + e);
#pragma unroll
            for (int f = 0; f < FF; f++) a = fmaf(f1[f], __ldg(w + f), a);
            x[e] += a;
        }
    }

    // logits for this (b, class)
    float lg[VV];
#pragma unroll
    for (int v = 0; v < VV; v++) {
        const float* w = out_w + v * EE;
        lg[v] = x[0] * __ldg(w) + x[1] * __ldg(w + 1) +
                x[2] * __ldg(w + 2) + x[3] * __ldg(w + 3);
    }
    g_logits[tid * 2 + 0] = make_float4(lg[0], lg[1], lg[2], lg[3]);
    g_logits[tid * 2 + 1] = make_float4(lg[4], lg[5], lg[6], lg[7]);
}

// ---------------------------------------------------------------------------
// Kernel 2: gather logits to every position. grid = 256 blocks x 128 thr.
// ---------------------------------------------------------------------------
__global__ void __launch_bounds__(128) gather_kernel(
        const int* __restrict__ token_ids, float4* __restrict__ out) {
    int t = blockIdx.x * blockDim.x + threadIdx.x;
    int b   = t >> 10;
    int tok = __ldg(token_ids + t);
    int idx = ((b << 3) + tok) * 2;
    float4 a = g_logits[idx];
    float4 c = g_logits[idx + 1];
    out[t * 2 + 0] = a;
    out[t * 2 + 1] = c;
}

// ---------------------------------------------------------------------------
// launch
// ---------------------------------------------------------------------------
extern "C" void kernel_launch(void* const* d_in, const int* in_sizes, int n_in,
                              void* d_out, int out_size) {
    const int*   token_ids = (const int*)d_in[0];
    const float* emb   = (const float*)d_in[1];
    const float* ln1_g = (const float*)d_in[2];
    const float* ln1_b = (const float*)d_in[3];
    const float* wqkv  = (const float*)d_in[4];
    const float* wo    = (const float*)d_in[5];
    const float* ln2_g = (const float*)d_in[6];
    const float* ln2_b = (const float*)d_in[7];
    const float* w1    = (const float*)d_in[8];
    const float* b1    = (const float*)d_in[9];
    const float* w2    = (const float*)d_in[10];
    const float* b2    = (const float*)d_in[11];
    const float* out_w = (const float*)d_in[12];
    float4* out = (float4*)d_out;

    classnet_kernel<<<1, NCT>>>(token_ids, emb, ln1_g, ln1_b, wqkv, wo,
                                ln2_g, ln2_b, w1, b1, w2, b2, out_w);
    gather_kernel<<<NT / 128, 128>>>(token_ids, out);
}